// round 3
// baseline (speedup 1.0000x reference)
#include <cuda_runtime.h>

// ---------------------------------------------------------------------------
// ChordProgressionLoss v3 — all-integer hot loop.
//   Row masks via magic-FADD + ALU mod-12 (no F2I).
//   Jaccard terms as exact bytes 60*i/(p+3-i) packed per-row into one u32
//   (one broadcast LDS + one PRMT). Window sums = PRMT gather + dp4a.
//   min(maj,mino) -> integer max; penalty accumulated as exact u64 integer.
//   Sim accumulated as fixed-point u64 (sim*2^30 = inter*R30[p,q]+A30[p,q]).
//   Integer sums are order-independent -> atomics are deterministic.
//   Each warp loads 128 rows, owns 125 (3-row overlap with next warp; no
//   cross-warp shuffles needed). Thread = 4 consecutive rows; windows within
//   thread need only 6 shuffles per 4 rows from lane+1.
// ---------------------------------------------------------------------------

#define WARPS_PER_BLOCK 4
#define THREADS (WARPS_PER_BLOCK * 32)
#define ROWS_PER_WARP 125

__device__ unsigned long long g_simSlots[32];
__device__ unsigned long long g_penSlots[32];
__device__ unsigned int       g_count = 0;

__device__ __forceinline__ unsigned pcbit(float f) {
    unsigned b  = __float_as_uint(f + 12582912.0f);  // 2^23*1.5: low bits = iv
    unsigned iv = b & 0x7Fu;                         // values are 0..127
    unsigned d  = (iv * 43u) >> 9;                   // floor(iv/12), exact iv<128
    return 1u << (iv - 12u * d);
}
__device__ __forceinline__ unsigned pcmask(float4 v) {
    return pcbit(v.x) | pcbit(v.y) | pcbit(v.z) | pcbit(v.w);
}
// gather {a.b0, b.b1, c.b2, d.b3}
__device__ __forceinline__ unsigned win4(unsigned a, unsigned b, unsigned c, unsigned d) {
    unsigned p1 = __byte_perm(a, b, 0x0050);
    unsigned p2 = __byte_perm(c, d, 0x0072);
    return __byte_perm(p1, p2, 0x5410);
}

__global__ __launch_bounds__(THREADS) void chord_fused(
    const float4* __restrict__ pred, const float4* __restrict__ targ,
    float* __restrict__ out, int T, int nWarps)
{
    __shared__ unsigned sT60[8];   // [p] = bytes {60*i/(p+3-i)} for i=0..3
    __shared__ uint2    sSim[24];  // [p*4+q] = {R30, A30}
    __shared__ bool     sLast;

    const int tid = threadIdx.x;
    if (tid < 8) {
        int p = tid; unsigned w = 0;
        for (int i = 0; i < 4; i++) {
            int dnm = p + 3 - i;
            unsigned t = (dnm > 0) ? (unsigned)((60 * i) / dnm) : 0u;
            w |= (t & 0xFFu) << (8 * i);
        }
        sT60[p] = w;
    }
    if (tid < 16) {
        int p = (tid >> 2) + 1, q = (tid & 3) + 1;
        double r = 1.0 / (((double)p + 12e-6) * ((double)q + 12e-6));
        unsigned R30 = (unsigned)__double2ll_rn(r * 1073741824.0);
        unsigned A30 = (unsigned)__double2ll_rn((1e-6 * (p + q) + 1.2e-11) * r * 1073741824.0);
        sSim[p * 4 + q] = make_uint2(R30, A30);
    }
    __syncthreads();

    const int lane = tid & 31;
    const int wid  = tid >> 5;
    const int warpGlobal = blockIdx.x * WARPS_PER_BLOCK + wid;

    unsigned long long simAcc = 0ull;
    unsigned penAcc = 0u;

    if (warpGlobal < nWarps) {
        const int rowBase = warpGlobal * ROWS_PER_WARP;
        const int local0  = lane * 4;
        const int r0      = rowBase + local0;

        unsigned BM[4], Bm[4];
        #pragma unroll
        for (int j = 0; j < 4; j++) {
            int r = r0 + j;
            bool inR = (r < T);
            float4 pv = inR ? pred[r] : make_float4(0.f, 0.f, 0.f, 0.f);
            float4 tv = inR ? targ[r] : make_float4(0.f, 0.f, 0.f, 0.f);
            unsigned pm = pcmask(pv);
            unsigned tm = pcmask(tv);
            int p  = __popc(pm);             // 1..4
            int q  = __popc(tm);
            int it = __popc(pm & tm);
            uint2 ra = sSim[p * 4 + q];
            if (inR && (local0 + j < ROWS_PER_WARP))
                simAcc += (unsigned long long)((unsigned)it * ra.x + ra.y);

            unsigned Tp = sT60[p];           // broadcast-friendly (4 words)
            // selector nibbles = intersection sizes vs the 3 distinct templates
            unsigned selM = __popc(pm & 0x091u) * 0x1001u
                          + (__popc(pm & 0x221u) << 4)
                          + (__popc(pm & 0x884u) << 8);
            unsigned selm = __popc(pm & 0x089u) * 0x1001u
                          + (__popc(pm & 0x121u) << 4)
                          + (__popc(pm & 0x484u) << 8);
            BM[j] = __byte_perm(Tp, 0, selM);   // bytes {t0,t1,t2,t0}
            Bm[j] = __byte_perm(Tp, 0, selm);
        }

        unsigned nM0 = __shfl_down_sync(0xffffffffu, BM[0], 1);
        unsigned nM1 = __shfl_down_sync(0xffffffffu, BM[1], 1);
        unsigned nM2 = __shfl_down_sync(0xffffffffu, BM[2], 1);
        unsigned nm0 = __shfl_down_sync(0xffffffffu, Bm[0], 1);
        unsigned nm1 = __shfl_down_sync(0xffffffffu, Bm[1], 1);
        unsigned nm2 = __shfl_down_sync(0xffffffffu, Bm[2], 1);

        unsigned WM[7] = { BM[0], BM[1], BM[2], BM[3], nM0, nM1, nM2 };
        unsigned Wm[7] = { Bm[0], Bm[1], Bm[2], Bm[3], nm0, nm1, nm2 };

        const int lastWin = T - 4;
        #pragma unroll
        for (int j = 0; j < 4; j++) {
            unsigned SM = __dp4a(win4(WM[j], WM[j+1], WM[j+2], WM[j+3]), 0x01010101u, 0u);
            unsigned Sm = __dp4a(win4(Wm[j], Wm[j+1], Wm[j+2], Wm[j+3]), 0x01010101u, 0u);
            if ((local0 + j < ROWS_PER_WARP) && (r0 + j <= lastWin))
                penAcc += (SM > Sm) ? SM : Sm;   // 240*(1-min(maj,mino))
        }
    }

    // warp reduction (exact integer adds -> order-independent)
    unsigned long long penW = (unsigned long long)penAcc;
    #pragma unroll
    for (int o = 16; o; o >>= 1) {
        simAcc += __shfl_xor_sync(0xffffffffu, simAcc, o);
        penW   += __shfl_xor_sync(0xffffffffu, penW,   o);
    }
    if (lane == 0) {
        int slot = warpGlobal & 31;
        atomicAdd(&g_simSlots[slot], simAcc);
        atomicAdd(&g_penSlots[slot], penW);
    }
    __syncthreads();
    if (tid == 0) {
        __threadfence();
        sLast = (atomicAdd(&g_count, 1u) == gridDim.x - 1);
    }
    __syncthreads();

    if (sLast && tid < 32) {
        __threadfence();
        unsigned long long s = *(volatile unsigned long long*)&g_simSlots[tid];
        unsigned long long p = *(volatile unsigned long long*)&g_penSlots[tid];
        #pragma unroll
        for (int o = 16; o; o >>= 1) {
            s += __shfl_xor_sync(0xffffffffu, s, o);
            p += __shfl_xor_sync(0xffffffffu, p, o);
        }
        if (tid == 0) {
            double simMean = ((double)s * (1.0 / 1073741824.0)) / (double)T;
            long long nWin = (long long)T - 3;
            double pen = (nWin > 0) ? (0.5 - (double)p / (480.0 * (double)nWin)) : 0.0;
            out[0] = (float)((1.0 - simMean) + pen);
        }
        g_simSlots[tid] = 0ull;     // self-reset for next graph replay
        g_penSlots[tid] = 0ull;
        if (tid == 0) g_count = 0;
    }
}

extern "C" void kernel_launch(void* const* d_in, const int* in_sizes, int n_in,
                              void* d_out, int out_size)
{
    const float4* pred = (const float4*)d_in[0];
    const float4* targ = (const float4*)d_in[1];
    int T1 = in_sizes[0] / 4;
    int T2 = in_sizes[1] / 4;
    int T = (T1 < T2) ? T1 : T2;

    int nWarps = (T + ROWS_PER_WARP - 1) / ROWS_PER_WARP;
    if (nWarps < 1) nWarps = 1;
    int blocks = (nWarps + WARPS_PER_BLOCK - 1) / WARPS_PER_BLOCK;

    chord_fused<<<blocks, THREADS>>>(pred, targ, (float*)d_out, T, nWarps);
}